// round 1
// baseline (speedup 1.0000x reference)
#include <cuda_runtime.h>
#include <cuda_bf16.h>

#define BMAX 32
#define NMAX 640

// Scratch (allocation-free rule: __device__ globals)
__device__ float g_c[BMAX][NMAX];      // token centers
__device__ float g_rsig[BMAX][NMAX];   // 1/sigma
__device__ float g_coef[BMAX][NMAX];   // pad? 0 : 1/(sigma*sqrt(2pi))
__device__ int   g_tok[BMAX][NMAX];    // merged token ids
__device__ float g_cumtot[BMAX];       // total duration per batch

// ---------------------------------------------------------------------------
// Kernel 1: merge blank/token pairs + cumsum + per-token params. One block/batch.
// ---------------------------------------------------------------------------
__global__ void prep_kernel(const int* __restrict__ text,
                            const int* __restrict__ durs,
                            int L, int N) {
    const int b   = blockIdx.x;
    const int tid = threadIdx.x;   // blockDim.x == 1024

    float dm = 0.f;
    int   tk = 0;
    if (tid < N) {
        if (tid == 0) {
            dm = (float)durs[b * L];
            tk = text[b * L];
        } else {
            dm = (float)(durs[b * L + 2 * tid - 1] + durs[b * L + 2 * tid]);
            tk = text[b * L + 2 * tid - 1];
        }
    }

    __shared__ float s[1024];
    s[tid] = (tid < N) ? dm : 0.f;
    // Hillis-Steele inclusive scan over 1024 slots (N <= 1024)
    for (int off = 1; off < 1024; off <<= 1) {
        __syncthreads();
        float v = (tid >= off) ? s[tid - off] : 0.f;
        __syncthreads();
        s[tid] += v;
    }
    __syncthreads();

    if (tid < N) {
        float cum = s[tid];
        float sig = dm * 0.5f + 1e-6f;          // d / SIGMA_C + EPS, SIGMA_C = 2
        g_c[b][tid]    = cum - 0.5f * dm;
        g_rsig[b][tid] = 1.0f / sig;
        g_coef[b][tid] = (tk == 0) ? 0.f : (0.3989422804014327f / sig); // 1/sqrt(2pi)/sig
        g_tok[b][tid]  = tk;
        if (tid == N - 1) g_cumtot[b] = cum;
    }
}

// ---------------------------------------------------------------------------
// Kernel 2: one block per (b, t). 128 threads; each owns output dims
// e, e+128, e+256 (E = 384). Windowed Gaussian weights + gather of embeddings.
// ---------------------------------------------------------------------------
__global__ void __launch_bounds__(128)
lenreg_kernel(const float* __restrict__ emb,
              float* __restrict__ out,
              int T, int N) {
    const int   b   = blockIdx.y;
    const int   ti  = blockIdx.x;
    const int   tid = threadIdx.x;
    const float t   = (float)ti + 0.5f;

    float* orow = out + ((size_t)(b * T + ti)) * 384;

    if (t >= g_cumtot[b]) {   // frames beyond sample duration -> zeros
        orow[tid]       = 0.f;
        orow[tid + 128] = 0.f;
        orow[tid + 256] = 0.f;
        return;
    }

    const float* __restrict__ cb    = g_c[b];
    const float* __restrict__ rsigb = g_rsig[b];
    const float* __restrict__ coefb = g_coef[b];
    const int*   __restrict__ tokb  = g_tok[b];

    // Window: contributions beyond |t-c| > 28 are < 1e-13 relative even with
    // an eps-only denominator (sigma <= 3). Centers are monotone -> binary search.
    const float W   = 28.f;
    const float tlo = t - W;
    const float thi = t + W;

    int lo = 0, hi = N;
    while (lo < hi) { int m = (lo + hi) >> 1; if (cb[m] < tlo) lo = m + 1; else hi = m; }
    const int nlo = lo;
    hi = N;
    while (lo < hi) { int m = (lo + hi) >> 1; if (cb[m] <= thi) lo = m + 1; else hi = m; }
    const int nhi = lo - 1;

    // Phase A: block-wide weight sum
    float sum = 0.f;
    for (int n = nlo + tid; n <= nhi; n += 128) {
        float z = (t - cb[n]) * rsigb[n];
        float a = -0.5f * z * z;
        if (a > -88.f) sum += coefb[n] * __expf(a);
    }
    __shared__ float red[4];
    #pragma unroll
    for (int o = 16; o; o >>= 1) sum += __shfl_down_sync(0xffffffffu, sum, o);
    if ((tid & 31) == 0) red[tid >> 5] = sum;
    __syncthreads();
    const float tot = red[0] + red[1] + red[2] + red[3];
    const float inv = 1.0f / (tot + 1e-6f);

    // Phase B: chunked shared broadcast of normalized weights, accumulate embed
    __shared__ float w_s[128];
    __shared__ int   tk_s[128];
    float a0 = 0.f, a1 = 0.f, a2 = 0.f;

    for (int base = nlo; base <= nhi; base += 128) {
        int   n  = base + tid;
        float w  = 0.f;
        int   tk = 0;
        if (n <= nhi) {
            float z = (t - cb[n]) * rsigb[n];
            float a = -0.5f * z * z;
            w  = (a > -88.f) ? coefb[n] * __expf(a) * inv : 0.f;
            tk = tokb[n];
        }
        __syncthreads();
        w_s[tid]  = w;
        tk_s[tid] = tk;
        __syncthreads();

        const int cnt = min(128, nhi - base + 1);
        for (int j = 0; j < cnt; j++) {
            float wj = w_s[j];
            if (wj != 0.f) {                 // uniform branch; skips pad/zero-dur
                const float* er = emb + tk_s[j] * 384;
                a0 += wj * er[tid];
                a1 += wj * er[tid + 128];
                a2 += wj * er[tid + 256];
            }
        }
    }

    orow[tid]       = a0;
    orow[tid + 128] = a1;
    orow[tid + 256] = a2;
}

// ---------------------------------------------------------------------------
extern "C" void kernel_launch(void* const* d_in, const int* in_sizes, int n_in,
                              void* d_out, int out_size) {
    const int*   text = (const int*)d_in[0];
    const int*   durs = (const int*)d_in[1];
    const float* emb  = (const float*)d_in[2];
    // d_in[3] = total_time scalar on device; T derived from out_size instead.
    float* out = (float*)d_out;

    const int B = 32;
    const int L = in_sizes[0] / B;        // 1025
    const int N = (L + 1) / 2;            // 513
    const int T = out_size / (B * 384);   // 2048

    prep_kernel<<<B, 1024>>>(text, durs, L, N);

    dim3 grid(T, B);
    lenreg_kernel<<<grid, 128>>>(emb, out, T, N);
}

// round 2
// speedup vs baseline: 2.5439x; 2.5439x over previous
#include <cuda_runtime.h>
#include <cuda_bf16.h>

#define BMAX 32
#define NMAX 640
#define TB   8          // frames per block

// Scratch (allocation-free rule: __device__ globals)
__device__ float g_c[BMAX][NMAX];      // token centers
__device__ float g_rsig[BMAX][NMAX];   // 1/sigma
__device__ float g_coef[BMAX][NMAX];   // pad? 0 : 1/(sigma*sqrt(2pi))
__device__ int   g_tok[BMAX][NMAX];    // merged token ids
__device__ float g_cumtot[BMAX];       // total duration per batch

// ---------------------------------------------------------------------------
// Kernel 1: merge blank/token pairs + cumsum + per-token params. One block/batch.
// ---------------------------------------------------------------------------
__global__ void prep_kernel(const int* __restrict__ text,
                            const int* __restrict__ durs,
                            int L, int N) {
    const int b   = blockIdx.x;
    const int tid = threadIdx.x;   // blockDim.x == 1024

    float dm = 0.f;
    int   tk = 0;
    if (tid < N) {
        if (tid == 0) {
            dm = (float)durs[b * L];
            tk = text[b * L];
        } else {
            dm = (float)(durs[b * L + 2 * tid - 1] + durs[b * L + 2 * tid]);
            tk = text[b * L + 2 * tid - 1];
        }
    }

    __shared__ float s[1024];
    s[tid] = (tid < N) ? dm : 0.f;
    for (int off = 1; off < 1024; off <<= 1) {
        __syncthreads();
        float v = (tid >= off) ? s[tid - off] : 0.f;
        __syncthreads();
        s[tid] += v;
    }
    __syncthreads();

    if (tid < N) {
        float cum = s[tid];
        float sig = dm * 0.5f + 1e-6f;          // d / SIGMA_C + EPS, SIGMA_C = 2
        g_c[b][tid]    = cum - 0.5f * dm;
        g_rsig[b][tid] = 1.0f / sig;
        g_coef[b][tid] = (tk == 0) ? 0.f : (0.3989422804014327f / sig);
        g_tok[b][tid]  = tk;
        if (tid == N - 1) g_cumtot[b] = cum;
    }
}

// ---------------------------------------------------------------------------
// Kernel 2: one block per (b, 8 frames). 128 threads; each thread owns output
// dims {tid, tid+128, tid+256} for all 8 frames (24 accumulators).
// ---------------------------------------------------------------------------
__global__ void __launch_bounds__(128)
lenreg_kernel(const float* __restrict__ emb,
              float* __restrict__ out,
              int T, int N) {
    const int b   = blockIdx.y;
    const int t0  = blockIdx.x * TB;
    const int tid = threadIdx.x;

    float* obase = out + ((size_t)b * T + t0) * 384;
    const float cumtot = g_cumtot[b];

    // Entire block beyond sample duration -> zeros and exit (~25% of blocks)
    if ((float)t0 + 0.5f >= cumtot) {
        #pragma unroll
        for (int tt = 0; tt < TB; tt++) {
            float* orow = obase + tt * 384;
            orow[tid] = 0.f; orow[tid + 128] = 0.f; orow[tid + 256] = 0.f;
        }
        return;
    }

    const float* __restrict__ cb    = g_c[b];
    const float* __restrict__ rsigb = g_rsig[b];
    const float* __restrict__ coefb = g_coef[b];
    const int*   __restrict__ tokb  = g_tok[b];

    // Window for the whole 8-frame group. Contributions beyond |t-c| > 28 are
    // < 1e-13 relative even against an eps-only denominator (sigma <= 3).
    const float tlo = (float)t0 + 0.5f - 28.f;
    const float thi = (float)t0 + ((float)TB - 0.5f) + 28.f;

    int lo = 0, hi = N;
    while (lo < hi) { int m = (lo + hi) >> 1; if (cb[m] < tlo) lo = m + 1; else hi = m; }
    const int nlo = lo;
    hi = N;
    while (lo < hi) { int m = (lo + hi) >> 1; if (cb[m] <= thi) lo = m + 1; else hi = m; }
    const int nhi = lo - 1;

    __shared__ float Wt[128 * TB];     // [token][frame] normalized weights
    __shared__ int   off_s[128];       // byte offsets into emb table
    __shared__ float ssum[TB];
    __shared__ float sinv[TB];

    float a0[TB], a1[TB], a2[TB];
    #pragma unroll
    for (int tt = 0; tt < TB; tt++) { a0[tt] = 0.f; a1[tt] = 0.f; a2[tt] = 0.f; }

    if (nhi >= nlo) {
        const bool multi = (nhi - nlo + 1) > 128;

        if (tid < TB) ssum[tid] = 0.f;
        __syncthreads();

        // ---- Pass A: raw weights + per-frame sums ----
        for (int base = nlo; base <= nhi; base += 128) {
            const int n = base + tid;
            if (n <= nhi) {
                float c  = cb[n];
                float rs = rsigb[n];
                float cf = coefb[n];
                #pragma unroll
                for (int tt = 0; tt < TB; tt++) {
                    float z = ((float)(t0 + tt) + 0.5f - c) * rs;
                    float a = -0.5f * z * z;
                    Wt[tid * TB + tt] = (a > -88.f) ? cf * __expf(a) : 0.f;
                }
                off_s[tid] = tokb[n] * 1536;   // *384 floats *4 bytes
            }
            __syncthreads();

            const int cnt  = min(128, nhi - base + 1);
            const int wrp  = tid >> 5;
            const int lane = tid & 31;
            for (int tt = wrp; tt < TB; tt += 4) {
                float s = 0.f;
                for (int j = lane; j < cnt; j += 32) s += Wt[j * TB + tt];
                #pragma unroll
                for (int o = 16; o; o >>= 1) s += __shfl_down_sync(0xffffffffu, s, o);
                if (lane == 0) atomicAdd(&ssum[tt], s);
            }
            __syncthreads();
        }

        if (tid < TB) {
            float t = (float)(t0 + tid) + 0.5f;
            sinv[tid] = (t < cumtot) ? 1.0f / (ssum[tid] + 1e-6f) : 0.f;
        }
        __syncthreads();

        // ---- Pass B: normalize + accumulate ----
        for (int base = nlo; base <= nhi; base += 128) {
            const int cnt = min(128, nhi - base + 1);

            if (multi) {   // rare fallback: recompute this chunk's raw weights
                const int n = base + tid;
                if (n <= nhi) {
                    float c  = cb[n];
                    float rs = rsigb[n];
                    float cf = coefb[n];
                    #pragma unroll
                    for (int tt = 0; tt < TB; tt++) {
                        float z = ((float)(t0 + tt) + 0.5f - c) * rs;
                        float a = -0.5f * z * z;
                        Wt[tid * TB + tt] = (a > -88.f) ? cf * __expf(a) : 0.f;
                    }
                    off_s[tid] = tokb[n] * 1536;
                }
                __syncthreads();
            }

            for (int idx = tid; idx < cnt * TB; idx += 128)
                Wt[idx] *= sinv[idx & (TB - 1)];
            __syncthreads();

            const float4* __restrict__ Wt4 = (const float4*)Wt;
            for (int j = 0; j < cnt; j++) {
                const float4 wA = Wt4[j * 2];          // frames 0..3 (broadcast)
                const float4 wB = Wt4[j * 2 + 1];      // frames 4..7
                const float* er = (const float*)((const char*)emb + off_s[j]);
                const float e0 = er[tid];
                const float e1 = er[tid + 128];
                const float e2 = er[tid + 256];
                a0[0] += wA.x * e0; a0[1] += wA.y * e0; a0[2] += wA.z * e0; a0[3] += wA.w * e0;
                a0[4] += wB.x * e0; a0[5] += wB.y * e0; a0[6] += wB.z * e0; a0[7] += wB.w * e0;
                a1[0] += wA.x * e1; a1[1] += wA.y * e1; a1[2] += wA.z * e1; a1[3] += wA.w * e1;
                a1[4] += wB.x * e1; a1[5] += wB.y * e1; a1[6] += wB.z * e1; a1[7] += wB.w * e1;
                a2[0] += wA.x * e2; a2[1] += wA.y * e2; a2[2] += wA.z * e2; a2[3] += wA.w * e2;
                a2[4] += wB.x * e2; a2[5] += wB.y * e2; a2[6] += wB.z * e2; a2[7] += wB.w * e2;
            }
            __syncthreads();   // protect Wt before next chunk overwrites
        }
    }

    #pragma unroll
    for (int tt = 0; tt < TB; tt++) {
        float* orow = obase + tt * 384;
        orow[tid]       = a0[tt];
        orow[tid + 128] = a1[tt];
        orow[tid + 256] = a2[tt];
    }
}

// ---------------------------------------------------------------------------
extern "C" void kernel_launch(void* const* d_in, const int* in_sizes, int n_in,
                              void* d_out, int out_size) {
    const int*   text = (const int*)d_in[0];
    const int*   durs = (const int*)d_in[1];
    const float* emb  = (const float*)d_in[2];
    float* out = (float*)d_out;

    const int B = 32;
    const int L = in_sizes[0] / B;        // 1025
    const int N = (L + 1) / 2;            // 513
    const int T = out_size / (B * 384);   // 2048

    prep_kernel<<<B, 1024>>>(text, durs, L, N);

    dim3 grid(T / TB, B);
    lenreg_kernel<<<grid, 128>>>(emb, out, T, N);
}